// round 16
// baseline (speedup 1.0000x reference)
#include <cuda_runtime.h>
#include <cstdint>

// ScaledDotProductAttention  B=4 H=16 S=2048 D=64
// out = [output (B,H,S,D) | attn (B,H,S,S)] f32.
// R16 = R12 minus bias smem staging (demand __ldg bias) -> smem 72.7 KB/CTA ->
// 3 CTAs/SM (12 warps). N-permuted K rows -> shuffle-free PV; K'/V' pre-permuted
// tf32 images; bit-packed mask; separate normalize kernel (optimal streamer).

#define NEG_INF -1000000000.0f

static constexpr int Bv = 4, Hv = 16, Sv = 2048, Dv = 64;
static constexpr int BM = 128, BN = 32, THREADS = 128, NKT = Sv / BN;   // 64 tiles
static constexpr int LDSK = 72;    // Q/K smem row stride (words)
static constexpr int LDSV = 136;   // V' pair-row stride (words)

// smem byte offsets: Q | K0 | K1 | V0 | V1
static constexpr int SQ  = 0;
static constexpr int QB  = BM * LDSK * 4;             // 36864
static constexpr int KTB = BN * LDSK * 4;             // 9216
static constexpr int VTB = 16 * LDSV * 4;             // 8704
static constexpr int SK0 = QB;
static constexpr int SK1 = SK0 + KTB;
static constexpr int SV0 = SK1 + KTB;
static constexpr int SV1 = SV0 + VTB;
static constexpr int SMEM_TOTAL = SV1 + VTB;          // 72704

static constexpr int MASK_WORDS_PER_ROW = Sv / 32;    // 64

__device__ float    g_inv[Bv * Hv * Sv];
__device__ uint32_t g_mask[Bv * Sv * MASK_WORDS_PER_ROW];   // 2 MB
__device__ uint32_t g_kperm[Bv * Hv * Sv * Dv];             // K': tf32, col pair-perm + row N-perm
__device__ uint32_t g_vperm[Bv * Hv * Sv * Dv];             // V': tf32, row-pair transp (32-row tiles)

__device__ __forceinline__ uint32_t s2u(const void* p) {
    uint32_t a;
    asm("{ .reg .u64 t; cvta.to.shared.u64 t, %1; cvt.u32.u64 %0, t; }" : "=r"(a) : "l"(p));
    return a;
}
__device__ __forceinline__ void cpa16(uint32_t dst, const void* src) {
    asm volatile("cp.async.cg.shared.global [%0], [%1], 16;" :: "r"(dst), "l"(src));
}
__device__ __forceinline__ uint32_t f2tf(float f) {
    uint32_t u;
    asm("cvt.rna.tf32.f32 %0, %1;" : "=r"(u) : "f"(f));
    return u;
}
__device__ __forceinline__ void st_cs1(float* p, float x) {
    asm volatile("st.global.cs.f32 [%0], %1;" :: "l"(p), "f"(x) : "memory");
}
__device__ __forceinline__ void mma8(float c[4], const uint32_t a[4], uint32_t b0, uint32_t b1) {
    asm volatile(
        "mma.sync.aligned.m16n8k8.row.col.f32.tf32.tf32.f32 "
        "{%0,%1,%2,%3}, {%4,%5,%6,%7}, {%8,%9}, {%0,%1,%2,%3};"
        : "+f"(c[0]), "+f"(c[1]), "+f"(c[2]), "+f"(c[3])
        : "r"(a[0]), "r"(a[1]), "r"(a[2]), "r"(a[3]), "r"(b0), "r"(b1));
}

// ---- pass 0a: pack mask to bits ----
__global__ __launch_bounds__(256)
void sdpa_pack_mask_kernel(const int* __restrict__ mask)
{
    int gid = blockIdx.x * blockDim.x + threadIdx.x;
    int4 m = *reinterpret_cast<const int4*>(mask + (size_t)gid * 4);
    uint32_t nib = (m.x != 0) | ((m.y != 0) << 1) | ((m.z != 0) << 2) | ((m.w != 0) << 3);
    uint32_t v = nib << (4 * (gid & 7));
    v |= __shfl_xor_sync(0xffffffffu, v, 1);
    v |= __shfl_xor_sync(0xffffffffu, v, 2);
    v |= __shfl_xor_sync(0xffffffffu, v, 4);
    if ((gid & 7) == 0) g_mask[gid >> 3] = v;
}

// ---- pass 0b: K' = tf32(K), cols pair-permuted AND rows N-permuted within 8-blocks ----
// slot(x) = 2x (x<4) else 2x-7 -> C-frag cols become (t4, t4+4) = PV A-frag cols.
__global__ __launch_bounds__(256)
void sdpa_prep_k_kernel(const float* __restrict__ k)
{
    int gid = blockIdx.x * blockDim.x + threadIdx.x;
    int row = gid >> 3, b8 = gid & 7;
    const float* src = k + (size_t)row * Dv + b8 * 8;
    float4 lo = *reinterpret_cast<const float4*>(src);
    float4 hi = *reinterpret_cast<const float4*>(src + 4);
    int x = row & 7;
    int slot = (x < 4) ? (2 * x) : (2 * x - 7);
    int drow = (row & ~7) | slot;
    uint32_t* dst = g_kperm + (size_t)drow * Dv + b8 * 8;
    *reinterpret_cast<uint4*>(dst)     = make_uint4(f2tf(lo.x), f2tf(hi.x), f2tf(lo.y), f2tf(hi.y));
    *reinterpret_cast<uint4*>(dst + 4) = make_uint4(f2tf(lo.z), f2tf(hi.z), f2tf(lo.w), f2tf(hi.w));
}

// ---- pass 0c: V' = tf32(V), 32-row tiles, row-pair transposed [p][c][2] ----
__global__ __launch_bounds__(256)
void sdpa_prep_v_kernel(const float* __restrict__ v)
{
    int gid = blockIdx.x * blockDim.x + threadIdx.x;   // over total/4 uint4s
    int tile = gid >> 9;                               // 512 uint4 per 32x64 tile
    int qq   = gid & 511;
    int p = qq >> 5, c = (qq & 31) * 2;                // 16 pair-rows x 32 uint4
    int r0 = (p >> 2) * 8 + (p & 3);
    const float* base = v + (size_t)tile * BN * Dv;
    float2 a = *reinterpret_cast<const float2*>(base + (size_t)r0 * Dv + c);
    float2 b = *reinterpret_cast<const float2*>(base + (size_t)(r0 + 4) * Dv + c);
    *reinterpret_cast<uint4*>(g_vperm + (size_t)gid * 4) =
        make_uint4(f2tf(a.x), f2tf(b.x), f2tf(a.y), f2tf(b.y));
}

__global__ __launch_bounds__(THREADS, 3)
void ScaledDotProductAttention_30253749633177_kernel(
    const float* __restrict__ q, const float* __restrict__ bias,
    float* __restrict__ out)
{
    extern __shared__ char smem[];
    const uint32_t sb = s2u(smem);
    uint32_t* sQ = (uint32_t*)(smem + SQ);

    const int b  = blockIdx.x & 3;
    const int h  = blockIdx.x >> 2;
    const int qt = blockIdx.y;
    const int tid = threadIdx.x;
    const int wid = tid >> 5, lane = tid & 31;
    const int g = lane >> 2, t4 = lane & 3;
    const int qbase = qt * BM, wrow = wid * 32;

    const size_t bh = (size_t)(b * Hv + h);
    const float*    qp = q + bh * Sv * Dv;
    const uint32_t* kp = g_kperm + bh * Sv * Dv;
    const uint32_t* vp = g_vperm + bh * Sv * Dv;   // tile kt at +kt*2048
    const float* biasp = bias + (size_t)h * Sv * Sv;
    const uint32_t* pm = g_mask + (size_t)b * Sv * MASK_WORDS_PER_ROW;
    float* op = out + bh * Sv * Dv;
    float* ap = out + (size_t)Bv * Hv * Sv * Dv + bh * (size_t)Sv * Sv;

    // ---- group 0: Q + K0 + V0 ----
    for (int i = tid; i < BM * Dv / 4; i += THREADS) {
        int r = i >> 4, c = (i & 15) * 4;
        cpa16(sb + SQ + (r * LDSK + c) * 4, qp + (size_t)(qbase + r) * Dv + c);
    }
    for (int i = tid; i < BN * Dv / 4; i += THREADS) {
        int r = i >> 4, c = (i & 15) * 4;
        cpa16(sb + SK0 + (r * LDSK + c) * 4, kp + (size_t)r * Dv + c);
    }
    for (int i = tid; i < 512; i += THREADS) {
        int p = i >> 5, u = i & 31;
        cpa16(sb + SV0 + (p * LDSV + u * 4) * 4, vp + (size_t)i * 4);
    }
    asm volatile("cp.async.commit_group;" ::: "memory");

    // wait group 0, rna-convert + pair-permute Q in place (one row per thread)
    asm volatile("cp.async.wait_group 0;" ::: "memory");
    __syncthreads();
    {
        uint32_t* qr = sQ + tid * LDSK;
        float f[64];
        #pragma unroll
        for (int i = 0; i < 16; i++) {
            float4 x = *reinterpret_cast<const float4*>(qr + i * 4);
            f[i*4+0] = x.x; f[i*4+1] = x.y; f[i*4+2] = x.z; f[i*4+3] = x.w;
        }
        #pragma unroll
        for (int b8 = 0; b8 < 8; b8++)
            #pragma unroll
            for (int i = 0; i < 4; i++) {
                qr[b8*8 + 2*i]     = f2tf(f[b8*8 + i]);
                qr[b8*8 + 2*i + 1] = f2tf(f[b8*8 + i + 4]);
            }
    }
    __syncthreads();

    const uint32_t* sQr0 = sQ + (wrow + g) * LDSK;
    const uint32_t* sQr1 = sQ + (wrow + 16 + g) * LDSK;
    const int rA0 = qbase + wrow + g;
    const int rA1 = qbase + wrow + 16 + g;

    float ls[2][2] = {{0.f, 0.f}, {0.f, 0.f}};
    float o[2][8][4];
    #pragma unroll
    for (int mb = 0; mb < 2; mb++)
        #pragma unroll
        for (int dt = 0; dt < 8; dt++)
            o[mb][dt][0] = o[mb][dt][1] = o[mb][dt][2] = o[mb][dt][3] = 0.f;

    for (int kt = 0; kt < NKT; kt++) {
        const int cur = kt & 1;
        if (kt + 1 < NKT) {
            const uint32_t dk = sb + (cur ? SK0 : SK1);
            const uint32_t dv = sb + (cur ? SV0 : SV1);
            const uint32_t* ks = kp + (size_t)(kt + 1) * BN * Dv;
            const uint32_t* vs = vp + (size_t)(kt + 1) * 2048;
            for (int i = tid; i < BN * Dv / 4; i += THREADS) {
                int r = i >> 4, c = (i & 15) * 4;
                cpa16(dk + (r * LDSK + c) * 4, ks + (size_t)r * Dv + c);
            }
            for (int i = tid; i < 512; i += THREADS) {
                int p = i >> 5, u = i & 31;
                cpa16(dv + (p * LDSV + u * 4) * 4, vs + (size_t)i * 4);
            }
            asm volatile("cp.async.commit_group;" ::: "memory");
            asm volatile("cp.async.wait_group 1;" ::: "memory");
        } else {
            asm volatile("cp.async.wait_group 0;" ::: "memory");
        }
        __syncthreads();

        const uint32_t* sK  = (const uint32_t*)(smem + (cur ? SK1 : SK0));
        const uint32_t* sVp = (const uint32_t*)(smem + (cur ? SV1 : SV0));

        const uint32_t mwA0 = pm[(size_t)rA0 * MASK_WORDS_PER_ROW + kt];
        const uint32_t mwB0 = pm[(size_t)(rA0 + 8) * MASK_WORDS_PER_ROW + kt];
        const uint32_t mwA1 = pm[(size_t)rA1 * MASK_WORDS_PER_ROW + kt];
        const uint32_t mwB1 = pm[(size_t)(rA1 + 8) * MASK_WORDS_PER_ROW + kt];

        // ---- QK (m32 x n32 per warp; LDS.64, no cvt; N-permuted output cols) ----
        float acc[2][4][4];
        #pragma unroll
        for (int mb = 0; mb < 2; mb++)
            #pragma unroll
            for (int nt = 0; nt < 4; nt++)
                acc[mb][nt][0] = acc[mb][nt][1] = acc[mb][nt][2] = acc[mb][nt][3] = 0.f;

        #pragma unroll
        for (int kk = 0; kk < 8; kk++) {
            const int co = kk * 8 + 2 * t4;
            uint32_t a0[4], a1[4];
            uint2 p0 = *reinterpret_cast<const uint2*>(sQr0 + co);
            uint2 p1 = *reinterpret_cast<const uint2*>(sQr0 + 8 * LDSK + co);
            uint2 p2 = *reinterpret_cast<const uint2*>(sQr1 + co);
            uint2 p3 = *reinterpret_cast<const uint2*>(sQr1 + 8 * LDSK + co);
            a0[0] = p0.x; a0[1] = p1.x; a0[2] = p0.y; a0[3] = p1.y;
            a1[0] = p2.x; a1[1] = p3.x; a1[2] = p2.y; a1[3] = p3.y;
            #pragma unroll
            for (int nt = 0; nt < 4; nt++) {
                uint2 bb = *reinterpret_cast<const uint2*>(sK + (nt * 8 + g) * LDSK + co);
                mma8(acc[0][nt], a0, bb.x, bb.y);
                mma8(acc[1][nt], a1, bb.x, bb.y);
            }
        }

        // ---- epilogue: bias via demand __ldg (L2-resident), mask bits, exp, store ----
        #pragma unroll
        for (int mb = 0; mb < 2; mb++) {
            const int rowA = (mb ? rA1 : rA0);
            const int rowB = rowA + 8;
            const uint32_t wa = (mb ? mwA1 : mwA0);
            const uint32_t wb = (mb ? mwB1 : mwB0);
            const float* bprA = biasp + (size_t)rowA * Sv + kt * BN;
            const float* bprB = biasp + (size_t)rowB * Sv + kt * BN;
            #pragma unroll
            for (int nt = 0; nt < 4; nt++) {
                const int c0 = nt * 8 + t4, c1 = c0 + 4;
                const int col0 = kt * BN + c0, col1 = kt * BN + c1;
                float bA0 = __ldg(bprA + c0);
                float bA1 = __ldg(bprA + c1);
                float bB0 = __ldg(bprB + c0);
                float bB1 = __ldg(bprB + c1);
                float s0 = (((wa >> c0) & 1u) ? acc[mb][nt][0] * 0.125f : NEG_INF) + bA0;
                float s1 = (((wa >> c1) & 1u) ? acc[mb][nt][1] * 0.125f : NEG_INF) + bA1;
                float s2 = (((wb >> c0) & 1u) ? acc[mb][nt][2] * 0.125f : NEG_INF) + bB0;
                float s3 = (((wb >> c1) & 1u) ? acc[mb][nt][3] * 0.125f : NEG_INF) + bB1;
                float e0 = __expf(fminf(s0, 60.f));
                float e1 = __expf(fminf(s1, 60.f));
                float e2 = __expf(fminf(s2, 60.f));
                float e3 = __expf(fminf(s3, 60.f));
                st_cs1(ap + (size_t)rowA * Sv + col0, e0);
                st_cs1(ap + (size_t)rowA * Sv + col1, e1);
                st_cs1(ap + (size_t)rowB * Sv + col0, e2);
                st_cs1(ap + (size_t)rowB * Sv + col1, e3);
                ls[mb][0] += e0 + e1;
                ls[mb][1] += e2 + e3;
                acc[mb][nt][0] = e0; acc[mb][nt][1] = e1;
                acc[mb][nt][2] = e2; acc[mb][nt][3] = e3;
            }
        }

        // ---- PV: A-frag = renamed C-frag (no shuffles), rna, MMA ----
        #pragma unroll
        for (int kk = 0; kk < 4; kk++) {
            uint32_t a0[4], a1[4];
            a0[0] = f2tf(acc[0][kk][0]); a0[1] = f2tf(acc[0][kk][2]);
            a0[2] = f2tf(acc[0][kk][1]); a0[3] = f2tf(acc[0][kk][3]);
            a1[0] = f2tf(acc[1][kk][0]); a1[1] = f2tf(acc[1][kk][2]);
            a1[2] = f2tf(acc[1][kk][1]); a1[3] = f2tf(acc[1][kk][3]);
            #pragma unroll
            for (int dt = 0; dt < 8; dt++) {
                uint2 vv = *reinterpret_cast<const uint2*>(sVp + (kk * 4 + t4) * LDSV + (dt * 8 + g) * 2);
                mma8(o[0][dt], a0, vv.x, vv.y);
                mma8(o[1][dt], a1, vv.x, vv.y);
            }
        }
        __syncthreads();
    }

    // ---- row sums -> inverses (t4 quad spans the 32 cols) ----
    #pragma unroll
    for (int mb = 0; mb < 2; mb++) {
        ls[mb][0] += __shfl_xor_sync(0xffffffffu, ls[mb][0], 1);
        ls[mb][0] += __shfl_xor_sync(0xffffffffu, ls[mb][0], 2);
        ls[mb][1] += __shfl_xor_sync(0xffffffffu, ls[mb][1], 1);
        ls[mb][1] += __shfl_xor_sync(0xffffffffu, ls[mb][1], 2);
    }
    const float il[2][2] = {{1.f / ls[0][0], 1.f / ls[0][1]},
                            {1.f / ls[1][0], 1.f / ls[1][1]}};

    if (t4 == 0) {
        #pragma unroll
        for (int mb = 0; mb < 2; mb++) {
            const int rowA = (mb ? rA1 : rA0);
            g_inv[bh * Sv + rowA]     = il[mb][0];
            g_inv[bh * Sv + rowA + 8] = il[mb][1];
        }
    }

    #pragma unroll
    for (int mb = 0; mb < 2; mb++) {
        const int rowA = (mb ? rA1 : rA0);
        const int rowB = rowA + 8;
        #pragma unroll
        for (int dt = 0; dt < 8; dt++) {
            int col = dt * 8 + 2 * t4;
            *reinterpret_cast<float2*>(op + (size_t)rowA * Dv + col) =
                make_float2(o[mb][dt][0] * il[mb][0], o[mb][dt][1] * il[mb][0]);
            *reinterpret_cast<float2*>(op + (size_t)rowB * Dv + col) =
                make_float2(o[mb][dt][2] * il[mb][1], o[mb][dt][3] * il[mb][1]);
        }
    }
}

// ---- pass 2: attn[row] *= 1/lsum[row] (high-occupancy streamer) ----
__global__ __launch_bounds__(256)
void sdpa_normalize_kernel(float4* __restrict__ attn, int64_t total4)
{
    int64_t stride = (int64_t)gridDim.x * blockDim.x;
    for (int64_t i = (int64_t)blockIdx.x * blockDim.x + threadIdx.x; i < total4; i += stride) {
        float inv = g_inv[i >> 9];
        float4 vv = __ldcs(attn + i);
        vv.x *= inv; vv.y *= inv; vv.z *= inv; vv.w *= inv;
        __stcs(attn + i, vv);
    }
}

extern "C" void kernel_launch(void* const* d_in, const int* in_sizes, int n_in,
                              void* d_out, int out_size)
{
    const float* q    = (const float*)d_in[0];
    const float* k    = (const float*)d_in[1];
    const float* v    = (const float*)d_in[2];
    const int*   mask = (const int*)d_in[3];
    const float* bias = (const float*)d_in[4];
    float* out = (float*)d_out;

    sdpa_pack_mask_kernel<<<Bv * Sv * Sv / 4 / 256, 256>>>(mask);
    sdpa_prep_k_kernel<<<Bv * Hv * Sv * 8 / 256, 256>>>(k);
    sdpa_prep_v_kernel<<<Bv * Hv * Sv * Dv / 4 / 256, 256>>>(v);

    cudaFuncSetAttribute(ScaledDotProductAttention_30253749633177_kernel,
                         cudaFuncAttributeMaxDynamicSharedMemorySize, SMEM_TOTAL);

    dim3 grid(Bv * Hv, Sv / BM);
    ScaledDotProductAttention_30253749633177_kernel<<<grid, THREADS, SMEM_TOTAL>>>(
        q, bias, out);

    float4* attn = (float4*)(out + (size_t)Bv * Hv * Sv * Dv);
    int64_t total4 = (int64_t)Bv * Hv * Sv * Sv / 4;
    sdpa_normalize_kernel<<<8192, 256>>>(attn, total4);
}

// round 17
// speedup vs baseline: 1.3028x; 1.3028x over previous
#include <cuda_runtime.h>
#include <cstdint>

// ScaledDotProductAttention  B=4 H=16 S=2048 D=64
// out = [output (B,H,S,D) | attn (B,H,S,S)] f32.
// R17 = R12 with the N-permutation moved from K to V': K natural (C-frag cols are
// contiguous pairs 2t4,2t4+1 -> STG.64 attn + float2 bias) while V' pair p=kk*4+t4
// holds kv rows (kk*8+2t4, kk*8+2t4+1) so PV stays shuffle-free via the same
// {c0,c2,c1,c3} register rename. BN=32; bias staged in smem; bit-packed mask.

#define NEG_INF -1000000000.0f

static constexpr int Bv = 4, Hv = 16, Sv = 2048, Dv = 64;
static constexpr int BM = 128, BN = 32, THREADS = 128, NKT = Sv / BN;   // 64 tiles
static constexpr int LDSK = 72;    // Q/K smem row stride (words)
static constexpr int LDSV = 136;   // V' pair-row stride (words)
static constexpr int LDSB = 40;    // bias row stride (words)

// smem byte offsets
static constexpr int SQ  = 0;
static constexpr int QB  = BM * LDSK * 4;             // 36864
static constexpr int KTB = BN * LDSK * 4;             // 9216
static constexpr int VTB = 16 * LDSV * 4;             // 8704
static constexpr int BTB = BM * LDSB * 4;             // 20480
static constexpr int SK0 = QB;
static constexpr int SK1 = SK0 + KTB;
static constexpr int SV0 = SK1 + KTB;
static constexpr int SV1 = SV0 + VTB;
static constexpr int SB0 = SV1 + VTB;
static constexpr int SB1 = SB0 + BTB;
static constexpr int SMEM_TOTAL = SB1 + BTB;          // 113664

static constexpr int MASK_WORDS_PER_ROW = Sv / 32;    // 64

__device__ float    g_inv[Bv * Hv * Sv];
__device__ uint32_t g_mask[Bv * Sv * MASK_WORDS_PER_ROW];   // 2 MB
__device__ uint32_t g_kperm[Bv * Hv * Sv * Dv];             // K': tf32, col pair-perm (rows natural)
__device__ uint32_t g_vperm[Bv * Hv * Sv * Dv];             // V': tf32, adjacent-row pairs per position

__device__ __forceinline__ uint32_t s2u(const void* p) {
    uint32_t a;
    asm("{ .reg .u64 t; cvta.to.shared.u64 t, %1; cvt.u32.u64 %0, t; }" : "=r"(a) : "l"(p));
    return a;
}
__device__ __forceinline__ void cpa16(uint32_t dst, const void* src) {
    asm volatile("cp.async.cg.shared.global [%0], [%1], 16;" :: "r"(dst), "l"(src));
}
__device__ __forceinline__ uint32_t f2tf(float f) {
    uint32_t u;
    asm("cvt.rna.tf32.f32 %0, %1;" : "=r"(u) : "f"(f));
    return u;
}
__device__ __forceinline__ void st_cs2(float* p, float x, float y) {
    asm volatile("st.global.cs.v2.f32 [%0], {%1, %2};" :: "l"(p), "f"(x), "f"(y) : "memory");
}
__device__ __forceinline__ void mma8(float c[4], const uint32_t a[4], uint32_t b0, uint32_t b1) {
    asm volatile(
        "mma.sync.aligned.m16n8k8.row.col.f32.tf32.tf32.f32 "
        "{%0,%1,%2,%3}, {%4,%5,%6,%7}, {%8,%9}, {%0,%1,%2,%3};"
        : "+f"(c[0]), "+f"(c[1]), "+f"(c[2]), "+f"(c[3])
        : "r"(a[0]), "r"(a[1]), "r"(a[2]), "r"(a[3]), "r"(b0), "r"(b1));
}

// ---- pass 0a: pack mask to bits ----
__global__ __launch_bounds__(256)
void sdpa_pack_mask_kernel(const int* __restrict__ mask)
{
    int gid = blockIdx.x * blockDim.x + threadIdx.x;
    int4 m = *reinterpret_cast<const int4*>(mask + (size_t)gid * 4);
    uint32_t nib = (m.x != 0) | ((m.y != 0) << 1) | ((m.z != 0) << 2) | ((m.w != 0) << 3);
    uint32_t v = nib << (4 * (gid & 7));
    v |= __shfl_xor_sync(0xffffffffu, v, 1);
    v |= __shfl_xor_sync(0xffffffffu, v, 2);
    v |= __shfl_xor_sync(0xffffffffu, v, 4);
    if ((gid & 7) == 0) g_mask[gid >> 3] = v;
}

// ---- pass 0b: K' = tf32(K), cols pair-permuted within each 8-block; rows NATURAL ----
__global__ __launch_bounds__(256)
void sdpa_prep_k_kernel(const float* __restrict__ k)
{
    int gid = blockIdx.x * blockDim.x + threadIdx.x;
    int row = gid >> 3, b8 = gid & 7;
    const float* src = k + (size_t)row * Dv + b8 * 8;
    float4 lo = *reinterpret_cast<const float4*>(src);
    float4 hi = *reinterpret_cast<const float4*>(src + 4);
    uint32_t* dst = g_kperm + (size_t)row * Dv + b8 * 8;
    *reinterpret_cast<uint4*>(dst)     = make_uint4(f2tf(lo.x), f2tf(hi.x), f2tf(lo.y), f2tf(hi.y));
    *reinterpret_cast<uint4*>(dst + 4) = make_uint4(f2tf(lo.z), f2tf(hi.z), f2tf(lo.w), f2tf(hi.w));
}

// ---- pass 0c: V' = tf32(V), 32-row tiles: pair p = kk*4+t4 holds ADJACENT kv rows
//               (kk*8 + 2*t4, kk*8 + 2*t4 + 1) -> positions (t4, t4+4) of step kk ----
__global__ __launch_bounds__(256)
void sdpa_prep_v_kernel(const float* __restrict__ v)
{
    int gid = blockIdx.x * blockDim.x + threadIdx.x;   // over total/4 uint4s
    int tile = gid >> 9;                               // 512 uint4 per 32x64 tile
    int qq   = gid & 511;
    int p = qq >> 5, c = (qq & 31) * 2;                // 16 pair-rows x 32 uint4
    int r0 = (p >> 2) * 8 + (p & 3) * 2;
    const float* base = v + (size_t)tile * BN * Dv;
    float2 a = *reinterpret_cast<const float2*>(base + (size_t)r0 * Dv + c);
    float2 b = *reinterpret_cast<const float2*>(base + (size_t)(r0 + 1) * Dv + c);
    *reinterpret_cast<uint4*>(g_vperm + (size_t)gid * 4) =
        make_uint4(f2tf(a.x), f2tf(b.x), f2tf(a.y), f2tf(b.y));
}

__global__ __launch_bounds__(THREADS, 2)
void ScaledDotProductAttention_30253749633177_kernel(
    const float* __restrict__ q, const float* __restrict__ bias,
    float* __restrict__ out)
{
    extern __shared__ char smem[];
    const uint32_t sb = s2u(smem);
    uint32_t* sQ = (uint32_t*)(smem + SQ);

    const int b  = blockIdx.x & 3;
    const int h  = blockIdx.x >> 2;
    const int qt = blockIdx.y;
    const int tid = threadIdx.x;
    const int wid = tid >> 5, lane = tid & 31;
    const int g = lane >> 2, t4 = lane & 3;
    const int qbase = qt * BM, wrow = wid * 32;

    const size_t bh = (size_t)(b * Hv + h);
    const float*    qp = q + bh * Sv * Dv;
    const uint32_t* kp = g_kperm + bh * Sv * Dv;
    const uint32_t* vp = g_vperm + bh * Sv * Dv;   // tile kt at +kt*2048
    const float* biasp = bias + (size_t)h * Sv * Sv;
    const uint32_t* pm = g_mask + (size_t)b * Sv * MASK_WORDS_PER_ROW;
    float* op = out + bh * Sv * Dv;
    float* ap = out + (size_t)Bv * Hv * Sv * Dv + bh * (size_t)Sv * Sv;

    // ---- group 0: Q + K0 + V0 + B0 ----
    for (int i = tid; i < BM * Dv / 4; i += THREADS) {
        int r = i >> 4, c = (i & 15) * 4;
        cpa16(sb + SQ + (r * LDSK + c) * 4, qp + (size_t)(qbase + r) * Dv + c);
    }
    for (int i = tid; i < BN * Dv / 4; i += THREADS) {
        int r = i >> 4, c = (i & 15) * 4;
        cpa16(sb + SK0 + (r * LDSK + c) * 4, kp + (size_t)r * Dv + c);
    }
    for (int i = tid; i < 512; i += THREADS) {
        int p = i >> 5, u = i & 31;
        cpa16(sb + SV0 + (p * LDSV + u * 4) * 4, vp + (size_t)i * 4);
    }
    for (int i = tid; i < BM * BN / 4; i += THREADS) {
        int r = i >> 3, c = (i & 7) * 4;
        cpa16(sb + SB0 + (r * LDSB + c) * 4, biasp + (size_t)(qbase + r) * Sv + c);
    }
    asm volatile("cp.async.commit_group;" ::: "memory");

    // wait group 0, rna-convert + pair-permute Q in place (one row per thread)
    asm volatile("cp.async.wait_group 0;" ::: "memory");
    __syncthreads();
    {
        uint32_t* qr = sQ + tid * LDSK;
        float f[64];
        #pragma unroll
        for (int i = 0; i < 16; i++) {
            float4 x = *reinterpret_cast<const float4*>(qr + i * 4);
            f[i*4+0] = x.x; f[i*4+1] = x.y; f[i*4+2] = x.z; f[i*4+3] = x.w;
        }
        #pragma unroll
        for (int b8 = 0; b8 < 8; b8++)
            #pragma unroll
            for (int i = 0; i < 4; i++) {
                qr[b8*8 + 2*i]     = f2tf(f[b8*8 + i]);
                qr[b8*8 + 2*i + 1] = f2tf(f[b8*8 + i + 4]);
            }
    }
    __syncthreads();

    const uint32_t* sQr0 = sQ + (wrow + g) * LDSK;
    const uint32_t* sQr1 = sQ + (wrow + 16 + g) * LDSK;
    const int rA0 = qbase + wrow + g;
    const int rA1 = qbase + wrow + 16 + g;
    const int lrA0 = wrow + g;
    const int lrA1 = wrow + 16 + g;

    float ls[2][2] = {{0.f, 0.f}, {0.f, 0.f}};
    float o[2][8][4];
    #pragma unroll
    for (int mb = 0; mb < 2; mb++)
        #pragma unroll
        for (int dt = 0; dt < 8; dt++)
            o[mb][dt][0] = o[mb][dt][1] = o[mb][dt][2] = o[mb][dt][3] = 0.f;

    for (int kt = 0; kt < NKT; kt++) {
        const int cur = kt & 1;
        if (kt + 1 < NKT) {
            const uint32_t dk = sb + (cur ? SK0 : SK1);
            const uint32_t dv = sb + (cur ? SV0 : SV1);
            const uint32_t db = sb + (cur ? SB0 : SB1);
            const uint32_t* ks = kp + (size_t)(kt + 1) * BN * Dv;
            const uint32_t* vs = vp + (size_t)(kt + 1) * 2048;
            const float*    bs = biasp + (size_t)(kt + 1) * BN;
            for (int i = tid; i < BN * Dv / 4; i += THREADS) {
                int r = i >> 4, c = (i & 15) * 4;
                cpa16(dk + (r * LDSK + c) * 4, ks + (size_t)r * Dv + c);
            }
            for (int i = tid; i < 512; i += THREADS) {
                int p = i >> 5, u = i & 31;
                cpa16(dv + (p * LDSV + u * 4) * 4, vs + (size_t)i * 4);
            }
            for (int i = tid; i < BM * BN / 4; i += THREADS) {
                int r = i >> 3, c = (i & 7) * 4;
                cpa16(db + (r * LDSB + c) * 4, bs + (size_t)(qbase + r) * Sv + c);
            }
            asm volatile("cp.async.commit_group;" ::: "memory");
            asm volatile("cp.async.wait_group 1;" ::: "memory");
        } else {
            asm volatile("cp.async.wait_group 0;" ::: "memory");
        }
        __syncthreads();

        const uint32_t* sK  = (const uint32_t*)(smem + (cur ? SK1 : SK0));
        const uint32_t* sVp = (const uint32_t*)(smem + (cur ? SV1 : SV0));
        const float*    sB  = (const float*)(smem + (cur ? SB1 : SB0));

        const uint32_t mwA0 = pm[(size_t)rA0 * MASK_WORDS_PER_ROW + kt];
        const uint32_t mwB0 = pm[(size_t)(rA0 + 8) * MASK_WORDS_PER_ROW + kt];
        const uint32_t mwA1 = pm[(size_t)rA1 * MASK_WORDS_PER_ROW + kt];
        const uint32_t mwB1 = pm[(size_t)(rA1 + 8) * MASK_WORDS_PER_ROW + kt];

        // ---- QK (m32 x n32 per warp; LDS.64, no cvt; natural cols) ----
        float acc[2][4][4];
        #pragma unroll
        for (int mb = 0; mb < 2; mb++)
            #pragma unroll
            for (int nt = 0; nt < 4; nt++)
                acc[mb][nt][0] = acc[mb][nt][1] = acc[mb][nt][2] = acc[mb][nt][3] = 0.f;

        #pragma unroll
        for (int kk = 0; kk < 8; kk++) {
            const int co = kk * 8 + 2 * t4;
            uint32_t a0[4], a1[4];
            uint2 p0 = *reinterpret_cast<const uint2*>(sQr0 + co);
            uint2 p1 = *reinterpret_cast<const uint2*>(sQr0 + 8 * LDSK + co);
            uint2 p2 = *reinterpret_cast<const uint2*>(sQr1 + co);
            uint2 p3 = *reinterpret_cast<const uint2*>(sQr1 + 8 * LDSK + co);
            a0[0] = p0.x; a0[1] = p1.x; a0[2] = p0.y; a0[3] = p1.y;
            a1[0] = p2.x; a1[1] = p3.x; a1[2] = p2.y; a1[3] = p3.y;
            #pragma unroll
            for (int nt = 0; nt < 4; nt++) {
                uint2 bb = *reinterpret_cast<const uint2*>(sK + (nt * 8 + g) * LDSK + co);
                mma8(acc[0][nt], a0, bb.x, bb.y);
                mma8(acc[1][nt], a1, bb.x, bb.y);
            }
        }

        // ---- epilogue: contiguous col pairs (2t4, 2t4+1): float2 bias + STG.64 attn ----
        #pragma unroll
        for (int mb = 0; mb < 2; mb++) {
            const int rowA = (mb ? rA1 : rA0);
            const int rowB = rowA + 8;
            const int lA = (mb ? lrA1 : lrA0);
            const uint32_t wa = (mb ? mwA1 : mwA0);
            const uint32_t wb = (mb ? mwB1 : mwB0);
            #pragma unroll
            for (int nt = 0; nt < 4; nt++) {
                const int c0 = nt * 8 + 2 * t4;
                const int col = kt * BN + c0;
                float2 bA = *reinterpret_cast<const float2*>(sB + lA * LDSB + c0);
                float2 bB = *reinterpret_cast<const float2*>(sB + (lA + 8) * LDSB + c0);
                const uint32_t sa = wa >> c0, sbb = wb >> c0;
                float s0 = ((sa & 1u)  ? acc[mb][nt][0] * 0.125f : NEG_INF) + bA.x;
                float s1 = ((sa & 2u)  ? acc[mb][nt][1] * 0.125f : NEG_INF) + bA.y;
                float s2 = ((sbb & 1u) ? acc[mb][nt][2] * 0.125f : NEG_INF) + bB.x;
                float s3 = ((sbb & 2u) ? acc[mb][nt][3] * 0.125f : NEG_INF) + bB.y;
                float e0 = __expf(fminf(s0, 60.f));
                float e1 = __expf(fminf(s1, 60.f));
                float e2 = __expf(fminf(s2, 60.f));
                float e3 = __expf(fminf(s3, 60.f));
                st_cs2(ap + (size_t)rowA * Sv + col, e0, e1);
                st_cs2(ap + (size_t)rowB * Sv + col, e2, e3);
                ls[mb][0] += e0 + e1;
                ls[mb][1] += e2 + e3;
                acc[mb][nt][0] = e0; acc[mb][nt][1] = e1;
                acc[mb][nt][2] = e2; acc[mb][nt][3] = e3;
            }
        }

        // ---- PV: A-frag = renamed C-frag (no shuffles), rna, MMA ----
        // position t4 of step kk = kv row kk*8+2t4 = c0; position t4+4 = row +1 = c1.
        #pragma unroll
        for (int kk = 0; kk < 4; kk++) {
            uint32_t a0[4], a1[4];
            a0[0] = f2tf(acc[0][kk][0]); a0[1] = f2tf(acc[0][kk][2]);
            a0[2] = f2tf(acc[0][kk][1]); a0[3] = f2tf(acc[0][kk][3]);
            a1[0] = f2tf(acc[1][kk][0]); a1[1] = f2tf(acc[1][kk][2]);
            a1[2] = f2tf(acc[1][kk][1]); a1[3] = f2tf(acc[1][kk][3]);
            #pragma unroll
            for (int dt = 0; dt < 8; dt++) {
                uint2 vv = *reinterpret_cast<const uint2*>(sVp + (kk * 4 + t4) * LDSV + (dt * 8 + g) * 2);
                mma8(o[0][dt], a0, vv.x, vv.y);
                mma8(o[1][dt], a1, vv.x, vv.y);
            }
        }
        __syncthreads();
    }

    // ---- row sums -> inverses (t4 quad spans the 32 cols) ----
    #pragma unroll
    for (int mb = 0; mb < 2; mb++) {
        ls[mb][0] += __shfl_xor_sync(0xffffffffu, ls[mb][0], 1);
        ls[mb][0] += __shfl_xor_sync(0xffffffffu, ls[mb][0], 2);
        ls[mb][1] += __shfl_xor_sync(0xffffffffu, ls[mb][1], 1);
        ls[mb][1] += __shfl_xor_sync(0xffffffffu, ls[mb][1], 2);
    }
    const float il[2][2] = {{1.f / ls[0][0], 1.f / ls[0][1]},
                            {1.f / ls[1][0], 1.f / ls[1][1]}};

    if (t4 == 0) {
        #pragma unroll
        for (int mb = 0; mb < 2; mb++) {
            const int rowA = (mb ? rA1 : rA0);
            g_inv[bh * Sv + rowA]     = il[mb][0];
            g_inv[bh * Sv + rowA + 8] = il[mb][1];
        }
    }

    #pragma unroll
    for (int mb = 0; mb < 2; mb++) {
        const int rowA = (mb ? rA1 : rA0);
        const int rowB = rowA + 8;
        #pragma unroll
        for (int dt = 0; dt < 8; dt++) {
            int col = dt * 8 + 2 * t4;
            *reinterpret_cast<float2*>(op + (size_t)rowA * Dv + col) =
                make_float2(o[mb][dt][0] * il[mb][0], o[mb][dt][1] * il[mb][0]);
            *reinterpret_cast<float2*>(op + (size_t)rowB * Dv + col) =
                make_float2(o[mb][dt][2] * il[mb][1], o[mb][dt][3] * il[mb][1]);
        }
    }
}

// ---- pass 2: attn[row] *= 1/lsum[row] (high-occupancy streamer) ----
__global__ __launch_bounds__(256)
void sdpa_normalize_kernel(float4* __restrict__ attn, int64_t total4)
{
    int64_t stride = (int64_t)gridDim.x * blockDim.x;
    for (int64_t i = (int64_t)blockIdx.x * blockDim.x + threadIdx.x; i < total4; i += stride) {
        float inv = g_inv[i >> 9];
        float4 vv = __ldcs(attn + i);
        vv.x *= inv; vv.y *= inv; vv.z *= inv; vv.w *= inv;
        __stcs(attn + i, vv);
    }
}

extern "C" void kernel_launch(void* const* d_in, const int* in_sizes, int n_in,
                              void* d_out, int out_size)
{
    const float* q    = (const float*)d_in[0];
    const float* k    = (const float*)d_in[1];
    const float* v    = (const float*)d_in[2];
    const int*   mask = (const int*)d_in[3];
    const float* bias = (const float*)d_in[4];
    float* out = (float*)d_out;

    sdpa_pack_mask_kernel<<<Bv * Sv * Sv / 4 / 256, 256>>>(mask);
    sdpa_prep_k_kernel<<<Bv * Hv * Sv * 8 / 256, 256>>>(k);
    sdpa_prep_v_kernel<<<Bv * Hv * Sv * Dv / 4 / 256, 256>>>(v);

    cudaFuncSetAttribute(ScaledDotProductAttention_30253749633177_kernel,
                         cudaFuncAttributeMaxDynamicSharedMemorySize, SMEM_TOTAL);

    dim3 grid(Bv * Hv, Sv / BM);
    ScaledDotProductAttention_30253749633177_kernel<<<grid, THREADS, SMEM_TOTAL>>>(
        q, bias, out);

    float4* attn = (float4*)(out + (size_t)Bv * Hv * Sv * Dv);
    int64_t total4 = (int64_t)Bv * Hv * Sv * Sv / 4;
    sdpa_normalize_kernel<<<8192, 256>>>(attn, total4);
}